// round 12
// baseline (speedup 1.0000x reference)
#include <cuda_runtime.h>
#include <cuda_bf16.h>
#include <math.h>
#include <stdint.h>

// ---------------------------------------------------------------------------
// AlignmentLayer B=4, C=2048, P=4096, HID=256 — HMMA edition v3.
//  * bf16 limb-split GEMMs (x*y ~ x1y1+x1y2+x2y1), fp32 accum
//  * 3-stage cp.async pipeline
//  * NO score materialization: scores epilogue does online row-max
//    (atomicMax, monotone) + threshold append of survivors to per-row lists.
//    Monotonicity of the global max guarantees the appended set is a
//    superset of the final survivor set (weight > 1e-5).
//  * select_accum reads only the lists, normalizes with the final max,
//    gathers V rows (L2-resident), writes out.
// ---------------------------------------------------------------------------

namespace cfg {
constexpr int B    = 4;
constexpr int C    = 2048;
constexpr int P    = 4096;
constexpr int HID  = 256;
constexpr int KMAX = 1024;
}
using namespace cfg;

// ---- scratch (static __device__, no runtime allocation) -------------------
__device__ float g_Vt[(size_t)B * P * C];            // 134 MB V [b][p][c]
__device__ float g_oT[(size_t)B * P * C];            // 134 MB out [b][q][c]
__device__ int   g_m   [B * P];                      // row max (ordered-int)
__device__ int   g_lcnt[B * P];                      // per-row list counters
__device__ int   g_lidx[(size_t)B * P * KMAX];       // 64 MB survivor cols
__device__ float g_ls  [(size_t)B * P * KMAX];       // 64 MB survivor scores
// bf16 limb planes
__device__ __nv_bfloat16 g_Xq[2][(size_t)B * P * C];   // query feats [b][p][c]
__device__ __nv_bfloat16 g_Xp[2][(size_t)B * P * C];   // prompt feats [b][p][c]
__device__ __nv_bfloat16 g_Wl[2][(size_t)HID * C];     // W [o][c]
__device__ __nv_bfloat16 g_Qh[2][(size_t)B * P * HID]; // Q limbs [b][p][o]
__device__ __nv_bfloat16 g_Kh[2][(size_t)B * P * HID]; // K limbs [b][p][o]

// ---------------------------------------------------------------------------
// helpers
// ---------------------------------------------------------------------------
__device__ __forceinline__ uint32_t smem_u32(const void* p) {
    uint32_t a;
    asm("{ .reg .u64 t; cvta.to.shared.u64 t, %1; cvt.u32.u64 %0, t; }"
        : "=r"(a) : "l"(p));
    return a;
}
__device__ __forceinline__ void ldm_x4(uint32_t (&r)[4], uint32_t addr) {
    asm volatile("ldmatrix.sync.aligned.m8n8.x4.shared.b16 {%0,%1,%2,%3}, [%4];"
                 : "=r"(r[0]), "=r"(r[1]), "=r"(r[2]), "=r"(r[3]) : "r"(addr));
}
__device__ __forceinline__ void ldm_x2(uint32_t (&r)[2], uint32_t addr) {
    asm volatile("ldmatrix.sync.aligned.m8n8.x2.shared.b16 {%0,%1}, [%2];"
                 : "=r"(r[0]), "=r"(r[1]) : "r"(addr));
}
__device__ __forceinline__ void mma16816(float (&c)[4], const uint32_t (&a)[4],
                                         const uint32_t (&b)[2]) {
    asm volatile(
        "mma.sync.aligned.m16n8k16.row.col.f32.bf16.bf16.f32 "
        "{%0,%1,%2,%3}, {%4,%5,%6,%7}, {%8,%9}, {%0,%1,%2,%3};"
        : "+f"(c[0]), "+f"(c[1]), "+f"(c[2]), "+f"(c[3])
        : "r"(a[0]), "r"(a[1]), "r"(a[2]), "r"(a[3]), "r"(b[0]), "r"(b[1]));
}
__device__ __forceinline__ void cp16(uint32_t saddr, const void* gaddr) {
    asm volatile("cp.async.cg.shared.global [%0], [%1], 16;"
                 :: "r"(saddr), "l"(gaddr));
}
__device__ __forceinline__ void cp_commit() {
    asm volatile("cp.async.commit_group;");
}
template <int N>
__device__ __forceinline__ void cp_wait() {
    asm volatile("cp.async.wait_group %0;" :: "n"(N));
}

// ordered-int encoding for float atomicMax (monotone)
__device__ __forceinline__ int ford(float f) {
    int i = __float_as_int(f);
    return i >= 0 ? i : (i ^ 0x7fffffff);
}
__device__ __forceinline__ float dford(int o) {
    return __int_as_float(o >= 0 ? o : (o ^ 0x7fffffff));
}

// Tile geometry: CTA 128x128, BK=32 (64B rows), 8 warps 2x4 (warp 64x32)
constexpr int BK = 32;
constexpr int TILE_BYTES_  = 128 * BK * 2;           // 8 KB per operand
constexpr int STAGE_BYTES_ = 2 * TILE_BYTES_;        // 16 KB (A+B)
constexpr int STAGES = 3;                            // 48 KB static smem

__device__ __forceinline__ uint32_t swz(int row, int kbyte) {
    return (uint32_t)(row * 64 + (kbyte ^ ((row & 3) << 4)));
}

__device__ __forceinline__ void load_tile(uint32_t sbase,
                                          const __nv_bfloat16* grow,
                                          size_t gstride, int tid) {
#pragma unroll
    for (int i = 0; i < 2; i++) {
        int idx = i * 256 + tid;
        int row = idx >> 2, slot = idx & 3;
        cp16(sbase + swz(row, slot * 16), grow + (size_t)row * gstride + slot * 8);
    }
}

__device__ __forceinline__ void mma_chunk(uint32_t sA, uint32_t sB, int lane,
                                          int wm, int wn, float (&acc)[4][4][4]) {
#pragma unroll
    for (int k16 = 0; k16 < 2; k16++) {
        uint32_t afr[4][4], bfr[4][2];
#pragma unroll
        for (int mi = 0; mi < 4; mi++) {
            int row = wm * 64 + mi * 16 + (lane & 15);
            int kb  = k16 * 32 + (lane >> 4) * 16;
            ldm_x4(afr[mi], sA + swz(row, kb));
        }
#pragma unroll
        for (int ni = 0; ni < 4; ni++) {
            int row = wn * 32 + ni * 8 + (lane & 7);
            int kb  = k16 * 32 + ((lane >> 3) & 1) * 16;
            ldm_x2(bfr[ni], sB + swz(row, kb));
        }
#pragma unroll
        for (int mi = 0; mi < 4; mi++)
#pragma unroll
            for (int ni = 0; ni < 4; ni++)
                mma16816(acc[mi][ni], afr[mi], bfr[ni]);
    }
}

// ---------------------------------------------------------------------------
// limb split: x = h1 + h2 (+ eps ~2^-18 |x|)
// ---------------------------------------------------------------------------
__device__ __forceinline__ void split2(float x, __nv_bfloat16& a, __nv_bfloat16& b) {
    a = __float2bfloat16(x);
    b = __float2bfloat16(x - __bfloat162float(a));
}

__global__ void split_w_kernel(const float* __restrict__ Wm) {
    int i = blockIdx.x * 256 + threadIdx.x;
    if (i < HID * C) {
        __nv_bfloat16 a, b;
        split2(Wm[i], a, b);
        g_Wl[0][i] = a; g_Wl[1][i] = b;
    }
}

__global__ void gm_init_kernel() {
    int i = blockIdx.x * 256 + threadIdx.x;
    if (i < B * P) { g_m[i] = 0x80000000; g_lcnt[i] = 0; }
}

// transpose X[b][c][p] -> limb planes [b][p][c] (+ fp32 Vt for prompt)
__global__ void trsplit_kernel(const float* __restrict__ X, int is_prompt) {
    __shared__ float tile[32][33];
    const int b = blockIdx.z;
    const float* ib = X + (size_t)b * C * P;
    const int c0 = blockIdx.x * 32;   // pixel block
    const int r0 = blockIdx.y * 32;   // channel block
    const int tx = threadIdx.x, ty = threadIdx.y;
#pragma unroll
    for (int j = 0; j < 32; j += 8)
        tile[ty + j][tx] = ib[(size_t)(r0 + ty + j) * P + c0 + tx];
    __syncthreads();
#pragma unroll
    for (int j = 0; j < 32; j += 8) {
        float v = tile[tx][ty + j];
        size_t o = ((size_t)b * P + c0 + ty + j) * C + r0 + tx;
        __nv_bfloat16 a, bb;
        split2(v, a, bb);
        if (is_prompt) {
            g_Vt[o] = v;
            g_Xp[0][o] = a; g_Xp[1][o] = bb;
        } else {
            g_Xq[0][o] = a; g_Xq[1][o] = bb;
        }
    }
}

// ---------------------------------------------------------------------------
// Projection GEMM (HMMA): Out[b][p][o] = bias[o] + sum_c X[b][p][c]*W[o][c]
// K' = 3*2048 folded limbs. grid (P/128, HID/128, 2B): z = sel*B + b.
// ---------------------------------------------------------------------------
__global__ __launch_bounds__(256) void mma_proj(const float* __restrict__ bias) {
    __shared__ __align__(16) char smem[STAGES * STAGE_BYTES_];
    const uint32_t sb = smem_u32(smem);

    const int tid = threadIdx.x, lane = tid & 31, wid = tid >> 5;
    const int wm = wid >> 2, wn = wid & 3;
    const int pt = blockIdx.x, ny = blockIdx.y;
    const int sel = blockIdx.z >> 2, b = blockIdx.z & 3;

    const __nv_bfloat16* Xpl[2] = { sel ? g_Xp[0] : g_Xq[0],
                                    sel ? g_Xp[1] : g_Xq[1] };

    float acc[4][4][4];
#pragma unroll
    for (int mi = 0; mi < 4; mi++)
#pragma unroll
        for (int ni = 0; ni < 4; ni++)
#pragma unroll
            for (int r = 0; r < 4; r++) acc[mi][ni][r] = 0.f;

    constexpr int NC = 192;
    auto gA = [&](int kc) -> const __nv_bfloat16* {
        int ph = kc >> 6;                    // 0,1 -> X1 ; 2 -> X2
        const __nv_bfloat16* pl = Xpl[ph == 2 ? 1 : 0];
        return pl + ((size_t)b * P + pt * 128) * C + (size_t)(kc & 63) * BK;
    };
    auto gB = [&](int kc) -> const __nv_bfloat16* {
        int ph = kc >> 6;                    // 0 -> W1 ; 1 -> W2 ; 2 -> W1
        const __nv_bfloat16* pl = g_Wl[ph == 1 ? 1 : 0];
        return pl + (size_t)(ny * 128) * C + (size_t)(kc & 63) * BK;
    };

#pragma unroll
    for (int s = 0; s < 2; s++) {
        load_tile(sb + s * STAGE_BYTES_, gA(s), C, tid);
        load_tile(sb + s * STAGE_BYTES_ + TILE_BYTES_, gB(s), C, tid);
        cp_commit();
    }

    for (int kc = 0; kc < NC; kc++) {
        const int cur = kc % 3;
        if (kc < NC - 1) cp_wait<1>(); else cp_wait<0>();
        __syncthreads();
        if (kc + 2 < NC) {
            const int nx = (kc + 2) % 3;
            load_tile(sb + nx * STAGE_BYTES_, gA(kc + 2), C, tid);
            load_tile(sb + nx * STAGE_BYTES_ + TILE_BYTES_, gB(kc + 2), C, tid);
            cp_commit();
        }
        mma_chunk(sb + cur * STAGE_BYTES_, sb + cur * STAGE_BYTES_ + TILE_BYTES_,
                  lane, wm, wn, acc);
    }

    // epilogue: bias add, limb split, write planes
    __nv_bfloat16* O1 = sel ? g_Kh[0] : g_Qh[0];
    __nv_bfloat16* O2 = sel ? g_Kh[1] : g_Qh[1];
#pragma unroll
    for (int mi = 0; mi < 4; mi++) {
#pragma unroll
        for (int ni = 0; ni < 4; ni++) {
            int n = ny * 128 + wn * 32 + ni * 8 + 2 * (lane & 3);
            float b0 = __ldg(bias + n), b1 = __ldg(bias + n + 1);
#pragma unroll
            for (int h = 0; h < 2; h++) {
                int prow = pt * 128 + wm * 64 + mi * 16 + (lane >> 2) + h * 8;
                size_t o = ((size_t)b * P + prow) * HID + n;
                float v0 = acc[mi][ni][h * 2 + 0] + b0;
                float v1 = acc[mi][ni][h * 2 + 1] + b1;
                __nv_bfloat16 a0, a1, c0, c1;
                split2(v0, a0, c0);
                split2(v1, a1, c1);
                *(__nv_bfloat162*)(O1 + o) = __nv_bfloat162(a0, a1);
                *(__nv_bfloat162*)(O2 + o) = __nv_bfloat162(c0, c1);
            }
        }
    }
}

// ---------------------------------------------------------------------------
// Scores GEMM (HMMA) + online survivor selection. NO score store.
// Per row-fragment: tile max -> atomicMax(g_m); threshold with the running
// max (monotone => appended set is a superset of the final survivor set);
// append (col, score) of survivors to the per-row list.
// grid (P/128, P/128, B).
// ---------------------------------------------------------------------------
__global__ __launch_bounds__(256) void mma_scores() {
    __shared__ __align__(16) char smem[STAGES * STAGE_BYTES_];
    const uint32_t sb = smem_u32(smem);

    const int tid = threadIdx.x, lane = tid & 31, wid = tid >> 5;
    const int wm = wid >> 2, wn = wid & 3;
    const int qt = blockIdx.x, kt = blockIdx.y, b = blockIdx.z;

    float acc[4][4][4];
#pragma unroll
    for (int mi = 0; mi < 4; mi++)
#pragma unroll
        for (int ni = 0; ni < 4; ni++)
#pragma unroll
            for (int r = 0; r < 4; r++) acc[mi][ni][r] = 0.f;

    constexpr int NC = 24;
    auto gA = [&](int kc) -> const __nv_bfloat16* {
        int ph = kc >> 3;                    // 0,1 -> Q1 ; 2 -> Q2
        const __nv_bfloat16* pl = g_Qh[ph == 2 ? 1 : 0];
        return pl + ((size_t)b * P + qt * 128) * HID + (size_t)(kc & 7) * BK;
    };
    auto gB = [&](int kc) -> const __nv_bfloat16* {
        int ph = kc >> 3;                    // 0 -> K1 ; 1 -> K2 ; 2 -> K1
        const __nv_bfloat16* pl = g_Kh[ph == 1 ? 1 : 0];
        return pl + ((size_t)b * P + kt * 128) * HID + (size_t)(kc & 7) * BK;
    };

#pragma unroll
    for (int s = 0; s < 2; s++) {
        load_tile(sb + s * STAGE_BYTES_, gA(s), HID, tid);
        load_tile(sb + s * STAGE_BYTES_ + TILE_BYTES_, gB(s), HID, tid);
        cp_commit();
    }

    for (int kc = 0; kc < NC; kc++) {
        const int cur = kc % 3;
        if (kc < NC - 1) cp_wait<1>(); else cp_wait<0>();
        __syncthreads();
        if (kc + 2 < NC) {
            const int nx = (kc + 2) % 3;
            load_tile(sb + nx * STAGE_BYTES_, gA(kc + 2), HID, tid);
            load_tile(sb + nx * STAGE_BYTES_ + TILE_BYTES_, gB(kc + 2), HID, tid);
            cp_commit();
        }
        mma_chunk(sb + cur * STAGE_BYTES_, sb + cur * STAGE_BYTES_ + TILE_BYTES_,
                  lane, wm, wn, acc);
    }

    // epilogue: online max + survivor append (no score store)
#pragma unroll
    for (int mi = 0; mi < 4; mi++) {
#pragma unroll
        for (int h = 0; h < 2; h++) {
            float rm = -1e30f;
#pragma unroll
            for (int ni = 0; ni < 4; ni++)
                rm = fmaxf(rm, fmaxf(acc[mi][ni][h * 2], acc[mi][ni][h * 2 + 1]));
            rm = fmaxf(rm, __shfl_xor_sync(0xffffffffu, rm, 1));
            rm = fmaxf(rm, __shfl_xor_sync(0xffffffffu, rm, 2));

            const int row = qt * 128 + wm * 64 + mi * 16 + (lane >> 2) + h * 8;
            const int gi  = b * P + row;

            float oldm = 0.f;
            if ((lane & 3) == 0) oldm = dford(atomicMax(&g_m[gi], ford(rm)));
            oldm = __shfl_sync(0xffffffffu, oldm, lane & ~3);
            const float thr = fmaxf(oldm, rm) - 11.5129255f;   // ln(1e5)

#pragma unroll
            for (int ni = 0; ni < 4; ni++) {
#pragma unroll
                for (int e = 0; e < 2; e++) {
                    float v = acc[mi][ni][h * 2 + e];
                    if (v > thr) {
                        int col = kt * 128 + wn * 32 + ni * 8 + 2 * (lane & 3) + e;
                        int slot = atomicAdd(&g_lcnt[gi], 1);
                        if (slot < KMAX) {
                            g_lidx[(size_t)gi * KMAX + slot] = col;
                            g_ls [(size_t)gi * KMAX + slot] = v;
                        }
                    }
                }
            }
        }
    }
}

// ---------------------------------------------------------------------------
// List-based softmax + sparse V accumulation. Reads only the survivor list.
// grid (P, B), 256 threads.
// ---------------------------------------------------------------------------
__global__ __launch_bounds__(256) void select_accum_kernel() {
    const int b = blockIdx.y;
    const int q = blockIdx.x;
    const int t = threadIdx.x;
    const int gi = b * P + q;

    __shared__ int   sidx[KMAX];
    __shared__ float se[KMAX];
    __shared__ float red[256];

    const int n = min(g_lcnt[gi], KMAX);
    const float m = dford(g_m[gi]);

    float lsum = 0.f;
    for (int i = t; i < n; i += 256) {
        int   c = g_lidx[(size_t)gi * KMAX + i];
        float s = g_ls [(size_t)gi * KMAX + i];
        float e = __expf(s - m);
        sidx[i] = c;
        se[i]   = e;
        lsum += e;
    }
    red[t] = lsum;
    __syncthreads();
    for (int s = 128; s > 0; s >>= 1) {
        if (t < s) red[t] += red[t + s];
        __syncthreads();
    }
    const float inv = 1.0f / red[0];

    const float4* Vb = (const float4*)(g_Vt + (size_t)b * P * C);
    const int t2 = t * 2;
    float4 a0 = make_float4(0.f, 0.f, 0.f, 0.f);
    float4 a1 = make_float4(0.f, 0.f, 0.f, 0.f);

    int j = 0;
    for (; j + 2 <= n; j += 2) {
        const float w0 = se[j], w1 = se[j + 1];
        const float4* v0 = Vb + (size_t)sidx[j]     * (C / 4);
        const float4* v1 = Vb + (size_t)sidx[j + 1] * (C / 4);
        float4 x0 = v0[t2], x1 = v0[t2 + 1];
        float4 y0 = v1[t2], y1 = v1[t2 + 1];
        a0.x += w0 * x0.x; a0.y += w0 * x0.y; a0.z += w0 * x0.z; a0.w += w0 * x0.w;
        a1.x += w0 * x1.x; a1.y += w0 * x1.y; a1.z += w0 * x1.z; a1.w += w0 * x1.w;
        a0.x += w1 * y0.x; a0.y += w1 * y0.y; a0.z += w1 * y0.z; a0.w += w1 * y0.w;
        a1.x += w1 * y1.x; a1.y += w1 * y1.y; a1.z += w1 * y1.z; a1.w += w1 * y1.w;
    }
    if (j < n) {
        const float w0 = se[j];
        const float4* v0 = Vb + (size_t)sidx[j] * (C / 4);
        float4 x0 = v0[t2], x1 = v0[t2 + 1];
        a0.x += w0 * x0.x; a0.y += w0 * x0.y; a0.z += w0 * x0.z; a0.w += w0 * x0.w;
        a1.x += w0 * x1.x; a1.y += w0 * x1.y; a1.z += w0 * x1.z; a1.w += w0 * x1.w;
    }

    a0.x *= inv; a0.y *= inv; a0.z *= inv; a0.w *= inv;
    a1.x *= inv; a1.y *= inv; a1.z *= inv; a1.w *= inv;

    float4* orow = (float4*)(g_oT + ((size_t)b * P + q) * C);
    orow[t2]     = a0;
    orow[t2 + 1] = a1;
}

// ---------------------------------------------------------------------------
// transpose outT[b][q][c] -> out[b][c][q]
// ---------------------------------------------------------------------------
__global__ void transpose_to_out(float* __restrict__ out) {
    __shared__ float tile[32][33];
    const int b = blockIdx.z;
    const float* ib = g_oT + (size_t)b * P * C;
    float* ob       = out  + (size_t)b * C * P;
    const int c0 = blockIdx.x * 32;
    const int r0 = blockIdx.y * 32;
    const int tx = threadIdx.x, ty = threadIdx.y;
#pragma unroll
    for (int j = 0; j < 32; j += 8)
        tile[ty + j][tx] = ib[(size_t)(r0 + ty + j) * C + c0 + tx];
    __syncthreads();
#pragma unroll
    for (int j = 0; j < 32; j += 8)
        ob[(size_t)(c0 + ty + j) * P + r0 + tx] = tile[tx][ty + j];
}

// ---------------------------------------------------------------------------
extern "C" void kernel_launch(void* const* d_in, const int* in_sizes, int n_in,
                              void* d_out, int out_size)
{
    (void)in_sizes; (void)n_in; (void)out_size;
    const float* qf   = (const float*)d_in[0];
    const float* pf   = (const float*)d_in[1];
    const float* Wm   = (const float*)d_in[2];
    const float* bias = (const float*)d_in[3];
    float* out = (float*)d_out;

    split_w_kernel<<<(HID * C + 255) / 256, 256>>>(Wm);
    gm_init_kernel<<<(B * P + 255) / 256, 256>>>();
    trsplit_kernel<<<dim3(P / 32, C / 32, B), dim3(32, 8)>>>(qf, 0);
    trsplit_kernel<<<dim3(P / 32, C / 32, B), dim3(32, 8)>>>(pf, 1);

    mma_proj<<<dim3(P / 128, HID / 128, 2 * B), 256>>>(bias);   // Q and K

    mma_scores<<<dim3(P / 128, P / 128, B), 256>>>();

    select_accum_kernel<<<dim3(P, B), 256>>>();
    transpose_to_out<<<dim3(C / 32, P / 32, B), dim3(32, 8)>>>(out);
}

// round 13
// speedup vs baseline: 1.1425x; 1.1425x over previous
#include <cuda_runtime.h>
#include <cuda_bf16.h>
#include <math.h>
#include <stdint.h>

// ---------------------------------------------------------------------------
// AlignmentLayer B=4, C=2048, P=4096, HID=256 — HMMA edition v4.
//  * bf16 limb-split GEMMs (x*y ~ x1y1+x1y2+x2y1), fp32 accum
//  * 3-stage cp.async pipeline
//  * NO score materialization: scores epilogue does online row-max
//    (atomicMax, monotone) + threshold append of provisional survivors.
//  * select_accum re-filters the list against the FINAL max (weight>1e-5)
//    before the expensive V gather; all listed entries still contribute to
//    the softmax denominator (superset => slightly more accurate).
// ---------------------------------------------------------------------------

namespace cfg {
constexpr int B    = 4;
constexpr int C    = 2048;
constexpr int P    = 4096;
constexpr int HID  = 256;
constexpr int KMAX = 1024;
}
using namespace cfg;

// ---- scratch (static __device__, no runtime allocation) -------------------
__device__ float g_Vt[(size_t)B * P * C];            // 134 MB V [b][p][c]
__device__ float g_oT[(size_t)B * P * C];            // 134 MB out [b][q][c]
__device__ int   g_m   [B * P];                      // row max (ordered-int)
__device__ int   g_lcnt[B * P];                      // per-row list counters
__device__ int   g_lidx[(size_t)B * P * KMAX];       // 64 MB survivor cols
__device__ float g_ls  [(size_t)B * P * KMAX];       // 64 MB survivor scores
// bf16 limb planes
__device__ __nv_bfloat16 g_Xq[2][(size_t)B * P * C];   // query feats [b][p][c]
__device__ __nv_bfloat16 g_Xp[2][(size_t)B * P * C];   // prompt feats [b][p][c]
__device__ __nv_bfloat16 g_Wl[2][(size_t)HID * C];     // W [o][c]
__device__ __nv_bfloat16 g_Qh[2][(size_t)B * P * HID]; // Q limbs [b][p][o]
__device__ __nv_bfloat16 g_Kh[2][(size_t)B * P * HID]; // K limbs [b][p][o]

// ---------------------------------------------------------------------------
// helpers
// ---------------------------------------------------------------------------
__device__ __forceinline__ uint32_t smem_u32(const void* p) {
    uint32_t a;
    asm("{ .reg .u64 t; cvta.to.shared.u64 t, %1; cvt.u32.u64 %0, t; }"
        : "=r"(a) : "l"(p));
    return a;
}
__device__ __forceinline__ void ldm_x4(uint32_t (&r)[4], uint32_t addr) {
    asm volatile("ldmatrix.sync.aligned.m8n8.x4.shared.b16 {%0,%1,%2,%3}, [%4];"
                 : "=r"(r[0]), "=r"(r[1]), "=r"(r[2]), "=r"(r[3]) : "r"(addr));
}
__device__ __forceinline__ void ldm_x2(uint32_t (&r)[2], uint32_t addr) {
    asm volatile("ldmatrix.sync.aligned.m8n8.x2.shared.b16 {%0,%1}, [%2];"
                 : "=r"(r[0]), "=r"(r[1]) : "r"(addr));
}
__device__ __forceinline__ void mma16816(float (&c)[4], const uint32_t (&a)[4],
                                         const uint32_t (&b)[2]) {
    asm volatile(
        "mma.sync.aligned.m16n8k16.row.col.f32.bf16.bf16.f32 "
        "{%0,%1,%2,%3}, {%4,%5,%6,%7}, {%8,%9}, {%0,%1,%2,%3};"
        : "+f"(c[0]), "+f"(c[1]), "+f"(c[2]), "+f"(c[3])
        : "r"(a[0]), "r"(a[1]), "r"(a[2]), "r"(a[3]), "r"(b[0]), "r"(b[1]));
}
__device__ __forceinline__ void cp16(uint32_t saddr, const void* gaddr) {
    asm volatile("cp.async.cg.shared.global [%0], [%1], 16;"
                 :: "r"(saddr), "l"(gaddr));
}
__device__ __forceinline__ void cp_commit() {
    asm volatile("cp.async.commit_group;");
}
template <int N>
__device__ __forceinline__ void cp_wait() {
    asm volatile("cp.async.wait_group %0;" :: "n"(N));
}

// ordered-int encoding for float atomicMax (monotone)
__device__ __forceinline__ int ford(float f) {
    int i = __float_as_int(f);
    return i >= 0 ? i : (i ^ 0x7fffffff);
}
__device__ __forceinline__ float dford(int o) {
    return __int_as_float(o >= 0 ? o : (o ^ 0x7fffffff));
}

// Tile geometry: CTA 128x128, BK=32 (64B rows), 8 warps 2x4 (warp 64x32)
constexpr int BK = 32;
constexpr int TILE_BYTES_  = 128 * BK * 2;           // 8 KB per operand
constexpr int STAGE_BYTES_ = 2 * TILE_BYTES_;        // 16 KB (A+B)
constexpr int STAGES = 3;                            // 48 KB static smem

__device__ __forceinline__ uint32_t swz(int row, int kbyte) {
    return (uint32_t)(row * 64 + (kbyte ^ ((row & 3) << 4)));
}

__device__ __forceinline__ void load_tile(uint32_t sbase,
                                          const __nv_bfloat16* grow,
                                          size_t gstride, int tid) {
#pragma unroll
    for (int i = 0; i < 2; i++) {
        int idx = i * 256 + tid;
        int row = idx >> 2, slot = idx & 3;
        cp16(sbase + swz(row, slot * 16), grow + (size_t)row * gstride + slot * 8);
    }
}

__device__ __forceinline__ void mma_chunk(uint32_t sA, uint32_t sB, int lane,
                                          int wm, int wn, float (&acc)[4][4][4]) {
#pragma unroll
    for (int k16 = 0; k16 < 2; k16++) {
        uint32_t afr[4][4], bfr[4][2];
#pragma unroll
        for (int mi = 0; mi < 4; mi++) {
            int row = wm * 64 + mi * 16 + (lane & 15);
            int kb  = k16 * 32 + (lane >> 4) * 16;
            ldm_x4(afr[mi], sA + swz(row, kb));
        }
#pragma unroll
        for (int ni = 0; ni < 4; ni++) {
            int row = wn * 32 + ni * 8 + (lane & 7);
            int kb  = k16 * 32 + ((lane >> 3) & 1) * 16;
            ldm_x2(bfr[ni], sB + swz(row, kb));
        }
#pragma unroll
        for (int mi = 0; mi < 4; mi++)
#pragma unroll
            for (int ni = 0; ni < 4; ni++)
                mma16816(acc[mi][ni], afr[mi], bfr[ni]);
    }
}

// ---------------------------------------------------------------------------
// limb split: x = h1 + h2 (+ eps ~2^-18 |x|)
// ---------------------------------------------------------------------------
__device__ __forceinline__ void split2(float x, __nv_bfloat16& a, __nv_bfloat16& b) {
    a = __float2bfloat16(x);
    b = __float2bfloat16(x - __bfloat162float(a));
}

__global__ void split_w_kernel(const float* __restrict__ Wm) {
    int i = blockIdx.x * 256 + threadIdx.x;
    if (i < HID * C) {
        __nv_bfloat16 a, b;
        split2(Wm[i], a, b);
        g_Wl[0][i] = a; g_Wl[1][i] = b;
    }
}

__global__ void gm_init_kernel() {
    int i = blockIdx.x * 256 + threadIdx.x;
    if (i < B * P) { g_m[i] = 0x80000000; g_lcnt[i] = 0; }
}

// transpose X[b][c][p] -> limb planes [b][p][c] (+ fp32 Vt for prompt)
__global__ void trsplit_kernel(const float* __restrict__ X, int is_prompt) {
    __shared__ float tile[32][33];
    const int b = blockIdx.z;
    const float* ib = X + (size_t)b * C * P;
    const int c0 = blockIdx.x * 32;   // pixel block
    const int r0 = blockIdx.y * 32;   // channel block
    const int tx = threadIdx.x, ty = threadIdx.y;
#pragma unroll
    for (int j = 0; j < 32; j += 8)
        tile[ty + j][tx] = ib[(size_t)(r0 + ty + j) * P + c0 + tx];
    __syncthreads();
#pragma unroll
    for (int j = 0; j < 32; j += 8) {
        float v = tile[tx][ty + j];
        size_t o = ((size_t)b * P + c0 + ty + j) * C + r0 + tx;
        __nv_bfloat16 a, bb;
        split2(v, a, bb);
        if (is_prompt) {
            g_Vt[o] = v;
            g_Xp[0][o] = a; g_Xp[1][o] = bb;
        } else {
            g_Xq[0][o] = a; g_Xq[1][o] = bb;
        }
    }
}

// ---------------------------------------------------------------------------
// Projection GEMM (HMMA): Out[b][p][o] = bias[o] + sum_c X[b][p][c]*W[o][c]
// K' = 3*2048 folded limbs. grid (P/128, HID/128, 2B): z = sel*B + b.
// ---------------------------------------------------------------------------
__global__ __launch_bounds__(256) void mma_proj(const float* __restrict__ bias) {
    __shared__ __align__(16) char smem[STAGES * STAGE_BYTES_];
    const uint32_t sb = smem_u32(smem);

    const int tid = threadIdx.x, lane = tid & 31, wid = tid >> 5;
    const int wm = wid >> 2, wn = wid & 3;
    const int pt = blockIdx.x, ny = blockIdx.y;
    const int sel = blockIdx.z >> 2, b = blockIdx.z & 3;

    const __nv_bfloat16* Xpl[2] = { sel ? g_Xp[0] : g_Xq[0],
                                    sel ? g_Xp[1] : g_Xq[1] };

    float acc[4][4][4];
#pragma unroll
    for (int mi = 0; mi < 4; mi++)
#pragma unroll
        for (int ni = 0; ni < 4; ni++)
#pragma unroll
            for (int r = 0; r < 4; r++) acc[mi][ni][r] = 0.f;

    constexpr int NC = 192;
    auto gA = [&](int kc) -> const __nv_bfloat16* {
        int ph = kc >> 6;                    // 0,1 -> X1 ; 2 -> X2
        const __nv_bfloat16* pl = Xpl[ph == 2 ? 1 : 0];
        return pl + ((size_t)b * P + pt * 128) * C + (size_t)(kc & 63) * BK;
    };
    auto gB = [&](int kc) -> const __nv_bfloat16* {
        int ph = kc >> 6;                    // 0 -> W1 ; 1 -> W2 ; 2 -> W1
        const __nv_bfloat16* pl = g_Wl[ph == 1 ? 1 : 0];
        return pl + (size_t)(ny * 128) * C + (size_t)(kc & 63) * BK;
    };

#pragma unroll
    for (int s = 0; s < 2; s++) {
        load_tile(sb + s * STAGE_BYTES_, gA(s), C, tid);
        load_tile(sb + s * STAGE_BYTES_ + TILE_BYTES_, gB(s), C, tid);
        cp_commit();
    }

    for (int kc = 0; kc < NC; kc++) {
        const int cur = kc % 3;
        if (kc < NC - 1) cp_wait<1>(); else cp_wait<0>();
        __syncthreads();
        if (kc + 2 < NC) {
            const int nx = (kc + 2) % 3;
            load_tile(sb + nx * STAGE_BYTES_, gA(kc + 2), C, tid);
            load_tile(sb + nx * STAGE_BYTES_ + TILE_BYTES_, gB(kc + 2), C, tid);
            cp_commit();
        }
        mma_chunk(sb + cur * STAGE_BYTES_, sb + cur * STAGE_BYTES_ + TILE_BYTES_,
                  lane, wm, wn, acc);
    }

    // epilogue: bias add, limb split, write planes
    __nv_bfloat16* O1 = sel ? g_Kh[0] : g_Qh[0];
    __nv_bfloat16* O2 = sel ? g_Kh[1] : g_Qh[1];
#pragma unroll
    for (int mi = 0; mi < 4; mi++) {
#pragma unroll
        for (int ni = 0; ni < 4; ni++) {
            int n = ny * 128 + wn * 32 + ni * 8 + 2 * (lane & 3);
            float b0 = __ldg(bias + n), b1 = __ldg(bias + n + 1);
#pragma unroll
            for (int h = 0; h < 2; h++) {
                int prow = pt * 128 + wm * 64 + mi * 16 + (lane >> 2) + h * 8;
                size_t o = ((size_t)b * P + prow) * HID + n;
                float v0 = acc[mi][ni][h * 2 + 0] + b0;
                float v1 = acc[mi][ni][h * 2 + 1] + b1;
                __nv_bfloat16 a0, a1, c0, c1;
                split2(v0, a0, c0);
                split2(v1, a1, c1);
                *(__nv_bfloat162*)(O1 + o) = __nv_bfloat162(a0, a1);
                *(__nv_bfloat162*)(O2 + o) = __nv_bfloat162(c0, c1);
            }
        }
    }
}

// ---------------------------------------------------------------------------
// Scores GEMM (HMMA) + online survivor selection. NO score store.
// grid (P/128, P/128, B).
// ---------------------------------------------------------------------------
__global__ __launch_bounds__(256) void mma_scores() {
    __shared__ __align__(16) char smem[STAGES * STAGE_BYTES_];
    const uint32_t sb = smem_u32(smem);

    const int tid = threadIdx.x, lane = tid & 31, wid = tid >> 5;
    const int wm = wid >> 2, wn = wid & 3;
    const int qt = blockIdx.x, kt = blockIdx.y, b = blockIdx.z;

    float acc[4][4][4];
#pragma unroll
    for (int mi = 0; mi < 4; mi++)
#pragma unroll
        for (int ni = 0; ni < 4; ni++)
#pragma unroll
            for (int r = 0; r < 4; r++) acc[mi][ni][r] = 0.f;

    constexpr int NC = 24;
    auto gA = [&](int kc) -> const __nv_bfloat16* {
        int ph = kc >> 3;                    // 0,1 -> Q1 ; 2 -> Q2
        const __nv_bfloat16* pl = g_Qh[ph == 2 ? 1 : 0];
        return pl + ((size_t)b * P + qt * 128) * HID + (size_t)(kc & 7) * BK;
    };
    auto gB = [&](int kc) -> const __nv_bfloat16* {
        int ph = kc >> 3;                    // 0 -> K1 ; 1 -> K2 ; 2 -> K1
        const __nv_bfloat16* pl = g_Kh[ph == 1 ? 1 : 0];
        return pl + ((size_t)b * P + kt * 128) * HID + (size_t)(kc & 7) * BK;
    };

#pragma unroll
    for (int s = 0; s < 2; s++) {
        load_tile(sb + s * STAGE_BYTES_, gA(s), HID, tid);
        load_tile(sb + s * STAGE_BYTES_ + TILE_BYTES_, gB(s), HID, tid);
        cp_commit();
    }

    for (int kc = 0; kc < NC; kc++) {
        const int cur = kc % 3;
        if (kc < NC - 1) cp_wait<1>(); else cp_wait<0>();
        __syncthreads();
        if (kc + 2 < NC) {
            const int nx = (kc + 2) % 3;
            load_tile(sb + nx * STAGE_BYTES_, gA(kc + 2), HID, tid);
            load_tile(sb + nx * STAGE_BYTES_ + TILE_BYTES_, gB(kc + 2), HID, tid);
            cp_commit();
        }
        mma_chunk(sb + cur * STAGE_BYTES_, sb + cur * STAGE_BYTES_ + TILE_BYTES_,
                  lane, wm, wn, acc);
    }

    // epilogue: online max + provisional survivor append (no score store)
#pragma unroll
    for (int mi = 0; mi < 4; mi++) {
#pragma unroll
        for (int h = 0; h < 2; h++) {
            float rm = -1e30f;
#pragma unroll
            for (int ni = 0; ni < 4; ni++)
                rm = fmaxf(rm, fmaxf(acc[mi][ni][h * 2], acc[mi][ni][h * 2 + 1]));
            rm = fmaxf(rm, __shfl_xor_sync(0xffffffffu, rm, 1));
            rm = fmaxf(rm, __shfl_xor_sync(0xffffffffu, rm, 2));

            const int row = qt * 128 + wm * 64 + mi * 16 + (lane >> 2) + h * 8;
            const int gi  = b * P + row;

            float oldm = 0.f;
            if ((lane & 3) == 0) oldm = dford(atomicMax(&g_m[gi], ford(rm)));
            oldm = __shfl_sync(0xffffffffu, oldm, lane & ~3);
            const float thr = fmaxf(oldm, rm) - 11.5129255f;   // ln(1e5)

#pragma unroll
            for (int ni = 0; ni < 4; ni++) {
#pragma unroll
                for (int e = 0; e < 2; e++) {
                    float v = acc[mi][ni][h * 2 + e];
                    if (v > thr) {
                        int col = kt * 128 + wn * 32 + ni * 8 + 2 * (lane & 3) + e;
                        int slot = atomicAdd(&g_lcnt[gi], 1);
                        if (slot < KMAX) {
                            g_lidx[(size_t)gi * KMAX + slot] = col;
                            g_ls [(size_t)gi * KMAX + slot] = v;
                        }
                    }
                }
            }
        }
    }
}

// ---------------------------------------------------------------------------
// List softmax + sparse V accumulation with FINAL-max re-filter.
// All listed entries feed the denominator; only entries with final weight
// > 1e-5 are gathered (restores the small gather set the lists inflated).
// grid (P, B), 256 threads.
// ---------------------------------------------------------------------------
__global__ __launch_bounds__(256) void select_accum_kernel() {
    const int b = blockIdx.y;
    const int q = blockIdx.x;
    const int t = threadIdx.x;
    const int gi = b * P + q;

    __shared__ int   sidx[KMAX];
    __shared__ float se[KMAX];
    __shared__ float red[256];
    __shared__ int cnt_sh;
    if (t == 0) cnt_sh = 0;
    __syncthreads();

    const int n = min(g_lcnt[gi], KMAX);
    const float m = dford(g_m[gi]);

    float lsum = 0.f;
    for (int i = t; i < n; i += 256) {
        float s = g_ls[(size_t)gi * KMAX + i];
        float e = __expf(s - m);
        lsum += e;                       // superset denominator (more accurate)
        if (e > 1e-5f) {                 // final-max filter before gather
            int slot = atomicAdd(&cnt_sh, 1);
            sidx[slot] = g_lidx[(size_t)gi * KMAX + i];
            se[slot]   = e;
        }
    }
    red[t] = lsum;
    __syncthreads();
    for (int s = 128; s > 0; s >>= 1) {
        if (t < s) red[t] += red[t + s];
        __syncthreads();
    }
    const float inv = 1.0f / red[0];
    const int nk = cnt_sh;

    const float4* Vb = (const float4*)(g_Vt + (size_t)b * P * C);
    const int t2 = t * 2;
    float4 a0 = make_float4(0.f, 0.f, 0.f, 0.f);
    float4 a1 = make_float4(0.f, 0.f, 0.f, 0.f);

    int j = 0;
    for (; j + 2 <= nk; j += 2) {
        const float w0 = se[j], w1 = se[j + 1];
        const float4* v0 = Vb + (size_t)sidx[j]     * (C / 4);
        const float4* v1 = Vb + (size_t)sidx[j + 1] * (C / 4);
        float4 x0 = v0[t2], x1 = v0[t2 + 1];
        float4 y0 = v1[t2], y1 = v1[t2 + 1];
        a0.x += w0 * x0.x; a0.y += w0 * x0.y; a0.z += w0 * x0.z; a0.w += w0 * x0.w;
        a1.x += w0 * x1.x; a1.y += w0 * x1.y; a1.z += w0 * x1.z; a1.w += w0 * x1.w;
        a0.x += w1 * y0.x; a0.y += w1 * y0.y; a0.z += w1 * y0.z; a0.w += w1 * y0.w;
        a1.x += w1 * y1.x; a1.y += w1 * y1.y; a1.z += w1 * y1.z; a1.w += w1 * y1.w;
    }
    if (j < nk) {
        const float w0 = se[j];
        const float4* v0 = Vb + (size_t)sidx[j] * (C / 4);
        float4 x0 = v0[t2], x1 = v0[t2 + 1];
        a0.x += w0 * x0.x; a0.y += w0 * x0.y; a0.z += w0 * x0.z; a0.w += w0 * x0.w;
        a1.x += w0 * x1.x; a1.y += w0 * x1.y; a1.z += w0 * x1.z; a1.w += w0 * x1.w;
    }

    a0.x *= inv; a0.y *= inv; a0.z *= inv; a0.w *= inv;
    a1.x *= inv; a1.y *= inv; a1.z *= inv; a1.w *= inv;

    float4* orow = (float4*)(g_oT + ((size_t)b * P + q) * C);
    orow[t2]     = a0;
    orow[t2 + 1] = a1;
}

// ---------------------------------------------------------------------------
// transpose outT[b][q][c] -> out[b][c][q]
// ---------------------------------------------------------------------------
__global__ void transpose_to_out(float* __restrict__ out) {
    __shared__ float tile[32][33];
    const int b = blockIdx.z;
    const float* ib = g_oT + (size_t)b * P * C;
    float* ob       = out  + (size_t)b * C * P;
    const int c0 = blockIdx.x * 32;
    const int r0 = blockIdx.y * 32;
    const int tx = threadIdx.x, ty = threadIdx.y;
#pragma unroll
    for (int j = 0; j < 32; j += 8)
        tile[ty + j][tx] = ib[(size_t)(r0 + ty + j) * C + c0 + tx];
    __syncthreads();
#pragma unroll
    for (int j = 0; j < 32; j += 8)
        ob[(size_t)(c0 + ty + j) * P + r0 + tx] = tile[tx][ty + j];
}

// ---------------------------------------------------------------------------
extern "C" void kernel_launch(void* const* d_in, const int* in_sizes, int n_in,
                              void* d_out, int out_size)
{
    (void)in_sizes; (void)n_in; (void)out_size;
    const float* qf   = (const float*)d_in[0];
    const float* pf   = (const float*)d_in[1];
    const float* Wm   = (const float*)d_in[2];
    const float* bias = (const float*)d_in[3];
    float* out = (float*)d_out;

    split_w_kernel<<<(HID * C + 255) / 256, 256>>>(Wm);
    gm_init_kernel<<<(B * P + 255) / 256, 256>>>();
    trsplit_kernel<<<dim3(P / 32, C / 32, B), dim3(32, 8)>>>(qf, 0);
    trsplit_kernel<<<dim3(P / 32, C / 32, B), dim3(32, 8)>>>(pf, 1);

    mma_proj<<<dim3(P / 128, HID / 128, 2 * B), 256>>>(bias);   // Q and K

    mma_scores<<<dim3(P / 128, P / 128, B), 256>>>();

    select_accum_kernel<<<dim3(P, B), 256>>>();
    transpose_to_out<<<dim3(C / 32, P / 32, B), dim3(32, 8)>>>(out);
}

// round 14
// speedup vs baseline: 1.4838x; 1.2986x over previous
#include <cuda_runtime.h>
#include <cuda_bf16.h>
#include <math.h>
#include <stdint.h>

// ---------------------------------------------------------------------------
// AlignmentLayer B=4, C=2048, P=4096, HID=256 — HMMA edition v5.
//  * bf16 limb-split GEMMs (x*y ~ x1y1+x1y2+x2y1), fp32 accum
//  * BK=64 macro-chunks, double-buffered cp.async (half the syncs of v4)
//  * online row-max + survivor-list selection in the scores epilogue
//  * select_accum re-filters with the final max before the V gather
// ---------------------------------------------------------------------------

namespace cfg {
constexpr int B    = 4;
constexpr int C    = 2048;
constexpr int P    = 4096;
constexpr int HID  = 256;
constexpr int KMAX = 1024;
}
using namespace cfg;

// ---- scratch (static __device__, no runtime allocation) -------------------
__device__ float g_Vt[(size_t)B * P * C];            // 134 MB V [b][p][c]
__device__ float g_oT[(size_t)B * P * C];            // 134 MB out [b][q][c]
__device__ int   g_m   [B * P];                      // row max (ordered-int)
__device__ int   g_lcnt[B * P];                      // per-row list counters
__device__ int   g_lidx[(size_t)B * P * KMAX];       // 64 MB survivor cols
__device__ float g_ls  [(size_t)B * P * KMAX];       // 64 MB survivor scores
// bf16 limb planes
__device__ __nv_bfloat16 g_Xq[2][(size_t)B * P * C];   // query feats [b][p][c]
__device__ __nv_bfloat16 g_Xp[2][(size_t)B * P * C];   // prompt feats [b][p][c]
__device__ __nv_bfloat16 g_Wl[2][(size_t)HID * C];     // W [o][c]
__device__ __nv_bfloat16 g_Qh[2][(size_t)B * P * HID]; // Q limbs [b][p][o]
__device__ __nv_bfloat16 g_Kh[2][(size_t)B * P * HID]; // K limbs [b][p][o]

// ---------------------------------------------------------------------------
// helpers
// ---------------------------------------------------------------------------
__device__ __forceinline__ uint32_t smem_u32(const void* p) {
    uint32_t a;
    asm("{ .reg .u64 t; cvta.to.shared.u64 t, %1; cvt.u32.u64 %0, t; }"
        : "=r"(a) : "l"(p));
    return a;
}
__device__ __forceinline__ void ldm_x4(uint32_t (&r)[4], uint32_t addr) {
    asm volatile("ldmatrix.sync.aligned.m8n8.x4.shared.b16 {%0,%1,%2,%3}, [%4];"
                 : "=r"(r[0]), "=r"(r[1]), "=r"(r[2]), "=r"(r[3]) : "r"(addr));
}
__device__ __forceinline__ void ldm_x2(uint32_t (&r)[2], uint32_t addr) {
    asm volatile("ldmatrix.sync.aligned.m8n8.x2.shared.b16 {%0,%1}, [%2];"
                 : "=r"(r[0]), "=r"(r[1]) : "r"(addr));
}
__device__ __forceinline__ void mma16816(float (&c)[4], const uint32_t (&a)[4],
                                         const uint32_t (&b)[2]) {
    asm volatile(
        "mma.sync.aligned.m16n8k16.row.col.f32.bf16.bf16.f32 "
        "{%0,%1,%2,%3}, {%4,%5,%6,%7}, {%8,%9}, {%0,%1,%2,%3};"
        : "+f"(c[0]), "+f"(c[1]), "+f"(c[2]), "+f"(c[3])
        : "r"(a[0]), "r"(a[1]), "r"(a[2]), "r"(a[3]), "r"(b[0]), "r"(b[1]));
}
__device__ __forceinline__ void cp16(uint32_t saddr, const void* gaddr) {
    asm volatile("cp.async.cg.shared.global [%0], [%1], 16;"
                 :: "r"(saddr), "l"(gaddr));
}
__device__ __forceinline__ void cp_commit() {
    asm volatile("cp.async.commit_group;");
}
template <int N>
__device__ __forceinline__ void cp_wait() {
    asm volatile("cp.async.wait_group %0;" :: "n"(N));
}

// ordered-int encoding for float atomicMax (monotone)
__device__ __forceinline__ int ford(float f) {
    int i = __float_as_int(f);
    return i >= 0 ? i : (i ^ 0x7fffffff);
}
__device__ __forceinline__ float dford(int o) {
    return __int_as_float(o >= 0 ? o : (o ^ 0x7fffffff));
}

// Tile geometry: CTA 128x128, BK=64 macro-chunks (128B rows), 8 warps 2x4
constexpr int BK = 64;
constexpr int TILE_BYTES_  = 128 * BK * 2;           // 16 KB per operand
constexpr int STAGE_BYTES_ = 2 * TILE_BYTES_;        // 32 KB (A+B)
constexpr int SMEM_GEMM    = 2 * STAGE_BYTES_;       // 64 KB double-buffer

// 128B-row swizzle: 8 x 16B slots per row, xor by (row&7)
__device__ __forceinline__ uint32_t swz(int row, int kbyte) {
    return (uint32_t)(row * 128 + (kbyte ^ ((row & 7) << 4)));
}

// Load one 128x64 bf16 tile via cp.async (4 x 16B per thread)
__device__ __forceinline__ void load_tile(uint32_t sbase,
                                          const __nv_bfloat16* grow,
                                          size_t gstride, int tid) {
#pragma unroll
    for (int i = 0; i < 4; i++) {
        int idx = i * 256 + tid;
        int row = idx >> 3, slot = idx & 7;
        cp16(sbase + swz(row, slot * 16), grow + (size_t)row * gstride + slot * 8);
    }
}

// One BK=64 macro-chunk of MMAs for this warp
__device__ __forceinline__ void mma_chunk(uint32_t sA, uint32_t sB, int lane,
                                          int wm, int wn, float (&acc)[4][4][4]) {
#pragma unroll
    for (int k16 = 0; k16 < 4; k16++) {
        uint32_t afr[4][4], bfr[4][2];
#pragma unroll
        for (int mi = 0; mi < 4; mi++) {
            int row = wm * 64 + mi * 16 + (lane & 15);
            int kb  = k16 * 32 + (lane >> 4) * 16;
            ldm_x4(afr[mi], sA + swz(row, kb));
        }
#pragma unroll
        for (int ni = 0; ni < 4; ni++) {
            int row = wn * 32 + ni * 8 + (lane & 7);
            int kb  = k16 * 32 + ((lane >> 3) & 1) * 16;
            ldm_x2(bfr[ni], sB + swz(row, kb));
        }
#pragma unroll
        for (int mi = 0; mi < 4; mi++)
#pragma unroll
            for (int ni = 0; ni < 4; ni++)
                mma16816(acc[mi][ni], afr[mi], bfr[ni]);
    }
}

// ---------------------------------------------------------------------------
// limb split: x = h1 + h2 (+ eps ~2^-18 |x|)
// ---------------------------------------------------------------------------
__device__ __forceinline__ void split2(float x, __nv_bfloat16& a, __nv_bfloat16& b) {
    a = __float2bfloat16(x);
    b = __float2bfloat16(x - __bfloat162float(a));
}

__global__ void split_w_kernel(const float* __restrict__ Wm) {
    int i = blockIdx.x * 256 + threadIdx.x;
    if (i < HID * C) {
        __nv_bfloat16 a, b;
        split2(Wm[i], a, b);
        g_Wl[0][i] = a; g_Wl[1][i] = b;
    }
    if (i < B * P) { g_m[i] = (int)0x80000000; g_lcnt[i] = 0; }
}

// transpose X[b][c][p] -> limb planes [b][p][c] (+ fp32 Vt for prompt)
__global__ void trsplit_kernel(const float* __restrict__ X, int is_prompt) {
    __shared__ float tile[32][33];
    const int b = blockIdx.z;
    const float* ib = X + (size_t)b * C * P;
    const int c0 = blockIdx.x * 32;   // pixel block
    const int r0 = blockIdx.y * 32;   // channel block
    const int tx = threadIdx.x, ty = threadIdx.y;
#pragma unroll
    for (int j = 0; j < 32; j += 8)
        tile[ty + j][tx] = ib[(size_t)(r0 + ty + j) * P + c0 + tx];
    __syncthreads();
#pragma unroll
    for (int j = 0; j < 32; j += 8) {
        float v = tile[tx][ty + j];
        size_t o = ((size_t)b * P + c0 + ty + j) * C + r0 + tx;
        __nv_bfloat16 a, bb;
        split2(v, a, bb);
        if (is_prompt) {
            g_Vt[o] = v;
            g_Xp[0][o] = a; g_Xp[1][o] = bb;
        } else {
            g_Xq[0][o] = a; g_Xq[1][o] = bb;
        }
    }
}

// ---------------------------------------------------------------------------
// Projection GEMM (HMMA): Out[b][p][o] = bias[o] + sum_c X[b][p][c]*W[o][c]
// K' = 3*2048 folded limbs, BK=64 -> NC=96. grid (P/128, HID/128, 2B).
// ---------------------------------------------------------------------------
__global__ __launch_bounds__(256) void mma_proj(const float* __restrict__ bias) {
    extern __shared__ __align__(16) char smem[];
    const uint32_t sb = smem_u32(smem);

    const int tid = threadIdx.x, lane = tid & 31, wid = tid >> 5;
    const int wm = wid >> 2, wn = wid & 3;
    const int pt = blockIdx.x, ny = blockIdx.y;
    const int sel = blockIdx.z >> 2, b = blockIdx.z & 3;

    const __nv_bfloat16* Xpl[2] = { sel ? g_Xp[0] : g_Xq[0],
                                    sel ? g_Xp[1] : g_Xq[1] };

    float acc[4][4][4];
#pragma unroll
    for (int mi = 0; mi < 4; mi++)
#pragma unroll
        for (int ni = 0; ni < 4; ni++)
#pragma unroll
            for (int r = 0; r < 4; r++) acc[mi][ni][r] = 0.f;

    constexpr int NC = 96;                   // 3 passes x 2048/64
    auto gA = [&](int kc) -> const __nv_bfloat16* {
        int ph = kc >> 5;                    // 0,1 -> X1 ; 2 -> X2
        const __nv_bfloat16* pl = Xpl[ph == 2 ? 1 : 0];
        return pl + ((size_t)b * P + pt * 128) * C + (size_t)(kc & 31) * BK;
    };
    auto gB = [&](int kc) -> const __nv_bfloat16* {
        int ph = kc >> 5;                    // 0 -> W1 ; 1 -> W2 ; 2 -> W1
        const __nv_bfloat16* pl = g_Wl[ph == 1 ? 1 : 0];
        return pl + (size_t)(ny * 128) * C + (size_t)(kc & 31) * BK;
    };

    load_tile(sb, gA(0), C, tid);
    load_tile(sb + TILE_BYTES_, gB(0), C, tid);
    cp_commit();

    for (int kc = 0; kc < NC; kc++) {
        const uint32_t cur = sb + (kc & 1) * STAGE_BYTES_;
        if (kc + 1 < NC) {
            const uint32_t nx = sb + ((kc + 1) & 1) * STAGE_BYTES_;
            load_tile(nx, gA(kc + 1), C, tid);
            load_tile(nx + TILE_BYTES_, gB(kc + 1), C, tid);
            cp_commit();
            cp_wait<1>();
        } else {
            cp_wait<0>();
        }
        __syncthreads();
        mma_chunk(cur, cur + TILE_BYTES_, lane, wm, wn, acc);
        __syncthreads();
    }

    // epilogue: bias add, limb split, write planes
    __nv_bfloat16* O1 = sel ? g_Kh[0] : g_Qh[0];
    __nv_bfloat16* O2 = sel ? g_Kh[1] : g_Qh[1];
#pragma unroll
    for (int mi = 0; mi < 4; mi++) {
#pragma unroll
        for (int ni = 0; ni < 4; ni++) {
            int n = ny * 128 + wn * 32 + ni * 8 + 2 * (lane & 3);
            float b0 = __ldg(bias + n), b1 = __ldg(bias + n + 1);
#pragma unroll
            for (int h = 0; h < 2; h++) {
                int prow = pt * 128 + wm * 64 + mi * 16 + (lane >> 2) + h * 8;
                size_t o = ((size_t)b * P + prow) * HID + n;
                float v0 = acc[mi][ni][h * 2 + 0] + b0;
                float v1 = acc[mi][ni][h * 2 + 1] + b1;
                __nv_bfloat16 a0, a1, c0, c1;
                split2(v0, a0, c0);
                split2(v1, a1, c1);
                *(__nv_bfloat162*)(O1 + o) = __nv_bfloat162(a0, a1);
                *(__nv_bfloat162*)(O2 + o) = __nv_bfloat162(c0, c1);
            }
        }
    }
}

// ---------------------------------------------------------------------------
// Scores GEMM (HMMA) + online survivor selection. NO score store.
// K' = 3*256, BK=64 -> NC=12. grid (P/128, P/128, B).
// ---------------------------------------------------------------------------
__global__ __launch_bounds__(256) void mma_scores() {
    extern __shared__ __align__(16) char smem[];
    const uint32_t sb = smem_u32(smem);

    const int tid = threadIdx.x, lane = tid & 31, wid = tid >> 5;
    const int wm = wid >> 2, wn = wid & 3;
    const int qt = blockIdx.x, kt = blockIdx.y, b = blockIdx.z;

    float acc[4][4][4];
#pragma unroll
    for (int mi = 0; mi < 4; mi++)
#pragma unroll
        for (int ni = 0; ni < 4; ni++)
#pragma unroll
            for (int r = 0; r < 4; r++) acc[mi][ni][r] = 0.f;

    constexpr int NC = 12;                   // 3 passes x 256/64
    auto gA = [&](int kc) -> const __nv_bfloat16* {
        int ph = kc >> 2;                    // 0,1 -> Q1 ; 2 -> Q2
        const __nv_bfloat16* pl = g_Qh[ph == 2 ? 1 : 0];
        return pl + ((size_t)b * P + qt * 128) * HID + (size_t)(kc & 3) * BK;
    };
    auto gB = [&](int kc) -> const __nv_bfloat16* {
        int ph = kc >> 2;                    // 0 -> K1 ; 1 -> K2 ; 2 -> K1
        const __nv_bfloat16* pl = g_Kh[ph == 1 ? 1 : 0];
        return pl + ((size_t)b * P + kt * 128) * HID + (size_t)(kc & 3) * BK;
    };

    load_tile(sb, gA(0), HID, tid);
    load_tile(sb + TILE_BYTES_, gB(0), HID, tid);
    cp_commit();

    for (int kc = 0; kc < NC; kc++) {
        const uint32_t cur = sb + (kc & 1) * STAGE_BYTES_;
        if (kc + 1 < NC) {
            const uint32_t nx = sb + ((kc + 1) & 1) * STAGE_BYTES_;
            load_tile(nx, gA(kc + 1), HID, tid);
            load_tile(nx + TILE_BYTES_, gB(kc + 1), HID, tid);
            cp_commit();
            cp_wait<1>();
        } else {
            cp_wait<0>();
        }
        __syncthreads();
        mma_chunk(cur, cur + TILE_BYTES_, lane, wm, wn, acc);
        __syncthreads();
    }

    // epilogue: online max + provisional survivor append (no score store)
#pragma unroll
    for (int mi = 0; mi < 4; mi++) {
#pragma unroll
        for (int h = 0; h < 2; h++) {
            float rm = -1e30f;
#pragma unroll
            for (int ni = 0; ni < 4; ni++)
                rm = fmaxf(rm, fmaxf(acc[mi][ni][h * 2], acc[mi][ni][h * 2 + 1]));
            rm = fmaxf(rm, __shfl_xor_sync(0xffffffffu, rm, 1));
            rm = fmaxf(rm, __shfl_xor_sync(0xffffffffu, rm, 2));

            const int row = qt * 128 + wm * 64 + mi * 16 + (lane >> 2) + h * 8;
            const int gi  = b * P + row;

            float oldm = 0.f;
            if ((lane & 3) == 0) oldm = dford(atomicMax(&g_m[gi], ford(rm)));
            oldm = __shfl_sync(0xffffffffu, oldm, lane & ~3);
            const float thr = fmaxf(oldm, rm) - 11.5129255f;   // ln(1e5)

#pragma unroll
            for (int ni = 0; ni < 4; ni++) {
#pragma unroll
                for (int e = 0; e < 2; e++) {
                    float v = acc[mi][ni][h * 2 + e];
                    if (v > thr) {
                        int col = kt * 128 + wn * 32 + ni * 8 + 2 * (lane & 3) + e;
                        int slot = atomicAdd(&g_lcnt[gi], 1);
                        if (slot < KMAX) {
                            g_lidx[(size_t)gi * KMAX + slot] = col;
                            g_ls [(size_t)gi * KMAX + slot] = v;
                        }
                    }
                }
            }
        }
    }
}

// ---------------------------------------------------------------------------
// List softmax + sparse V accumulation with FINAL-max re-filter.
// grid (P, B), 256 threads.
// ---------------------------------------------------------------------------
__global__ __launch_bounds__(256) void select_accum_kernel() {
    const int b = blockIdx.y;
    const int q = blockIdx.x;
    const int t = threadIdx.x;
    const int gi = b * P + q;

    __shared__ int   sidx[KMAX];
    __shared__ float se[KMAX];
    __shared__ float red[256];
    __shared__ int cnt_sh;
    if (t == 0) cnt_sh = 0;
    __syncthreads();

    const int n = min(g_lcnt[gi], KMAX);
    const float m = dford(g_m[gi]);

    float lsum = 0.f;
    for (int i = t; i < n; i += 256) {
        float s = g_ls[(size_t)gi * KMAX + i];
        float e = __expf(s - m);
        lsum += e;                       // superset denominator
        if (e > 1e-5f) {                 // final-max filter before gather
            int slot = atomicAdd(&cnt_sh, 1);
            sidx[slot] = g_lidx[(size_t)gi * KMAX + i];
            se[slot]   = e;
        }
    }
    red[t] = lsum;
    __syncthreads();
    for (int s = 128; s > 0; s >>= 1) {
        if (t < s) red[t] += red[t + s];
        __syncthreads();
    }
    const float inv = 1.0f / red[0];
    const int nk = cnt_sh;

    const float4* Vb = (const float4*)(g_Vt + (size_t)b * P * C);
    const int t2 = t * 2;
    float4 a0 = make_float4(0.f, 0.f, 0.f, 0.f);
    float4 a1 = make_float4(0.f, 0.f, 0.f, 0.f);

    int j = 0;
    for (; j + 2 <= nk; j += 2) {
        const float w0 = se[j], w1 = se[j + 1];
        const float4* v0 = Vb + (size_t)sidx[j]     * (C / 4);
        const float4* v1 = Vb + (size_t)sidx[j + 1] * (C / 4);
        float4 x0 = v0[t2], x1 = v0[t2 + 1];
        float4 y0 = v1[t2], y1 = v1[t2 + 1];
        a0.x += w0 * x0.x; a0.y += w0 * x0.y; a0.z += w0 * x0.z; a0.w += w0 * x0.w;
        a1.x += w0 * x1.x; a1.y += w0 * x1.y; a1.z += w0 * x1.z; a1.w += w0 * x1.w;
        a0.x += w1 * y0.x; a0.y += w1 * y0.y; a0.z += w1 * y0.z; a0.w += w1 * y0.w;
        a1.x += w1 * y1.x; a1.y += w1 * y1.y; a1.z += w1 * y1.z; a1.w += w1 * y1.w;
    }
    if (j < nk) {
        const float w0 = se[j];
        const float4* v0 = Vb + (size_t)sidx[j] * (C / 4);
        float4 x0 = v0[t2], x1 = v0[t2 + 1];
        a0.x += w0 * x0.x; a0.y += w0 * x0.y; a0.z += w0 * x0.z; a0.w += w0 * x0.w;
        a1.x += w0 * x1.x; a1.y += w0 * x1.y; a1.z += w0 * x1.z; a1.w += w0 * x1.w;
    }

    a0.x *= inv; a0.y *= inv; a0.z *= inv; a0.w *= inv;
    a1.x *= inv; a1.y *= inv; a1.z *= inv; a1.w *= inv;

    float4* orow = (float4*)(g_oT + ((size_t)b * P + q) * C);
    orow[t2]     = a0;
    orow[t2 + 1] = a1;
}

// ---------------------------------------------------------------------------
// transpose outT[b][q][c] -> out[b][c][q]
// ---------------------------------------------------------------------------
__global__ void transpose_to_out(float* __restrict__ out) {
    __shared__ float tile[32][33];
    const int b = blockIdx.z;
    const float* ib = g_oT + (size_t)b * P * C;
    float* ob       = out  + (size_t)b * C * P;
    const int c0 = blockIdx.x * 32;
    const int r0 = blockIdx.y * 32;
    const int tx = threadIdx.x, ty = threadIdx.y;
#pragma unroll
    for (int j = 0; j < 32; j += 8)
        tile[ty + j][tx] = ib[(size_t)(r0 + ty + j) * C + c0 + tx];
    __syncthreads();
#pragma unroll
    for (int j = 0; j < 32; j += 8)
        ob[(size_t)(c0 + ty + j) * P + r0 + tx] = tile[tx][ty + j];
}

// ---------------------------------------------------------------------------
extern "C" void kernel_launch(void* const* d_in, const int* in_sizes, int n_in,
                              void* d_out, int out_size)
{
    (void)in_sizes; (void)n_in; (void)out_size;
    const float* qf   = (const float*)d_in[0];
    const float* pf   = (const float*)d_in[1];
    const float* Wm   = (const float*)d_in[2];
    const float* bias = (const float*)d_in[3];
    float* out = (float*)d_out;

    static int attr_done = 0;
    if (!attr_done) {
        cudaFuncSetAttribute(mma_proj,
                             cudaFuncAttributeMaxDynamicSharedMemorySize, SMEM_GEMM);
        cudaFuncSetAttribute(mma_scores,
                             cudaFuncAttributeMaxDynamicSharedMemorySize, SMEM_GEMM);
        attr_done = 1;
    }

    split_w_kernel<<<(HID * C + 255) / 256, 256>>>(Wm);
    trsplit_kernel<<<dim3(P / 32, C / 32, B), dim3(32, 8)>>>(qf, 0);
    trsplit_kernel<<<dim3(P / 32, C / 32, B), dim3(32, 8)>>>(pf, 1);

    mma_proj<<<dim3(P / 128, HID / 128, 2 * B), 256, SMEM_GEMM>>>(bias);

    mma_scores<<<dim3(P / 128, P / 128, B), 256, SMEM_GEMM>>>();

    select_accum_kernel<<<dim3(P, B), 256>>>();
    transpose_to_out<<<dim3(C / 32, P / 32, B), dim3(32, 8)>>>(out);
}